// round 3
// baseline (speedup 1.0000x reference)
#include <cuda_runtime.h>
#include <cuda_bf16.h>

// Problem constants (SAGEEncoder: N=50000, E=800000, IN=128, HID=128, OUT=64)
#define NMAX 50000
#define EMAX 800000
#define D_IN 128
#define D_HID 128
#define D_OUT 64

// ---------------- scratch (static device globals; no allocation) -------------
__device__ __align__(16) int   g_deg[NMAX];
__device__ __align__(16) int   g_rowstart[NMAX + 1];
__device__ __align__(16) int   g_cursor[NMAX];
__device__ __align__(16) int   g_csr[EMAX];
__device__ __align__(16) float g_t1[(size_t)NMAX * 256]; // [n][0:128)=feat@Wself1, [128:256)=feat@Wneigh1
__device__ __align__(16) float g_h1[(size_t)NMAX * 128]; // relu'd layer-1 output
__device__ __align__(16) float g_t2[(size_t)NMAX * 128]; // [n][0:64)=h1@Wself2, [64:128)=h1@Wneigh2
__device__ int g_is64;                                   // 1 if edge indices are int64, 0 if int32

// ---------------- index dtype detection --------------------------------------
// If indices are int64, every high 32-bit word is 0 (values in [0,50000)).
// If int32, odd 32-bit words are random node ids -> essentially never all zero.
__global__ void detect_kernel(const int* __restrict__ idx32, int E) {
    __shared__ int nz;
    if (threadIdx.x == 0) nz = 0;
    __syncthreads();
    int i = threadIdx.x;               // 0..255 ; 2*i+1 < 512 <= E, safe for both dtypes
    if (idx32[2 * i + 1] != 0) atomicAdd(&nz, 1);
    __syncthreads();
    if (threadIdx.x == 0) g_is64 = (nz == 0) ? 1 : 0;
}

__device__ __forceinline__ int load_idx(const void* p, int e, int is64) {
    if (is64) return (int)((const long long*)p)[e];
    return ((const int*)p)[e];
}

// ---------------- CSR build --------------------------------------------------
__global__ void zero_deg_kernel(int n) {
    int i = blockIdx.x * blockDim.x + threadIdx.x;
    if (i < n) g_deg[i] = 0;
}

__global__ void hist_kernel(const void* __restrict__ dst, int E) {
    int is64 = g_is64;
    for (int e = blockIdx.x * blockDim.x + threadIdx.x; e < E; e += gridDim.x * blockDim.x)
        atomicAdd(&g_deg[load_idx(dst, e, is64)], 1);
}

// single-block exclusive scan over degrees -> rowstart, cursor
__global__ void scan_kernel(int n, int E) {
    __shared__ int part[1024];
    int tid = threadIdx.x;
    int chunk = (n + 1023) / 1024;
    int lo = tid * chunk;
    int hi = min(lo + chunk, n);
    int s = 0;
    for (int i = lo; i < hi; i++) s += g_deg[i];
    part[tid] = s;
    __syncthreads();
    for (int off = 1; off < 1024; off <<= 1) {
        int v = (tid >= off) ? part[tid - off] : 0;
        __syncthreads();
        part[tid] += v;
        __syncthreads();
    }
    int run = (tid == 0) ? 0 : part[tid - 1];
    for (int i = lo; i < hi; i++) {
        g_rowstart[i] = run;
        g_cursor[i]   = run;
        run += g_deg[i];
    }
    if (tid == 1023) g_rowstart[n] = E;
}

__global__ void scatter_kernel(const void* __restrict__ src,
                               const void* __restrict__ dst, int E) {
    int is64 = g_is64;
    for (int e = blockIdx.x * blockDim.x + threadIdx.x; e < E; e += gridDim.x * blockDim.x) {
        int d = load_idx(dst, e, is64);
        int pos = atomicAdd(&g_cursor[d], 1);
        g_csr[pos] = load_idx(src, e, is64);
    }
}

// ---------------- fused dual-weight SGEMM ------------------------------------
// C[M x 2*halfN] = A[M x K] @ [W0 | W1]; W0/W1 are [K x halfN] row-major.
// layer==1: A = Aext (feat), C = g_t1.  layer==2: A = g_h1, C = g_t2.
#define BM 64
#define BN 64
#define BK 16
#define TM 4
#define TN 4

__global__ __launch_bounds__(256) void gemm_dual_kernel(
    const float* __restrict__ Aext,
    const float* __restrict__ W0,
    const float* __restrict__ W1,
    int M, int K, int halfN, int layer)
{
    const float* __restrict__ A = (layer == 1) ? Aext : g_h1;
    float* __restrict__ C       = (layer == 1) ? g_t1 : g_t2;

    const int N  = 2 * halfN;
    const int bn = blockIdx.x * BN;
    const int bm = blockIdx.y * BM;
    const float* W = (bn < halfN) ? W0 : W1;
    const int wcol0 = (bn < halfN) ? bn : bn - halfN;

    __shared__ float As[BM][BK];
    __shared__ float Ws[BK][BN];

    float acc[TM][TN];
#pragma unroll
    for (int i = 0; i < TM; i++)
#pragma unroll
        for (int j = 0; j < TN; j++) acc[i][j] = 0.f;

    const int tid = threadIdx.x;
    const int tx = tid % 16;          // -> BN/TN columns
    const int ty = tid / 16;          // -> BM/TM rows

    for (int k0 = 0; k0 < K; k0 += BK) {
#pragma unroll
        for (int i = tid; i < BM * BK; i += 256) {
            int r = i / BK, c = i % BK;
            int row = bm + r;
            As[r][c] = (row < M) ? A[(size_t)row * K + k0 + c] : 0.f;
        }
#pragma unroll
        for (int i = tid; i < BK * BN; i += 256) {
            int r = i / BN, c = i % BN;
            Ws[r][c] = W[(size_t)(k0 + r) * halfN + wcol0 + c];
        }
        __syncthreads();

#pragma unroll
        for (int kk = 0; kk < BK; kk++) {
            float a[TM], w[TN];
#pragma unroll
            for (int i = 0; i < TM; i++) a[i] = As[ty * TM + i][kk];
#pragma unroll
            for (int j = 0; j < TN; j++) w[j] = Ws[kk][tx * TN + j];
#pragma unroll
            for (int i = 0; i < TM; i++)
#pragma unroll
                for (int j = 0; j < TN; j++) acc[i][j] += a[i] * w[j];
        }
        __syncthreads();
    }

#pragma unroll
    for (int i = 0; i < TM; i++) {
        int row = bm + ty * TM + i;
        if (row < M) {
            float4 v = make_float4(acc[i][0], acc[i][1], acc[i][2], acc[i][3]);
            *reinterpret_cast<float4*>(&C[(size_t)row * N + bn + tx * TN]) = v;
        }
    }
}

// ---------------- aggregation + epilogue -------------------------------------
// layer 1: h1[i][j] = relu( t1[i][j] + (sum_{in-edges} t1[src][128+j]) / deg + b1[j] )
__global__ void agg_epilogue1_kernel(const float* __restrict__ b1, int n) {
    int node = blockIdx.x * blockDim.y + threadIdx.y;
    if (node >= n) return;
    int j = threadIdx.x;   // 0..127
    int beg = g_rowstart[node];
    int end = g_rowstart[node + 1];
    float acc = 0.f;
    for (int e = beg; e < end; e++) {
        int s = g_csr[e];
        acc += g_t1[(size_t)s * 256 + 128 + j];
    }
    float inv = 1.f / fmaxf((float)(end - beg), 1.f);
    float v = g_t1[(size_t)node * 256 + j] + acc * inv + b1[j];
    g_h1[(size_t)node * 128 + j] = fmaxf(v, 0.f);
}

// layer 2: out[i][j] = t2[i][j] + (sum t2[src][64+j]) / deg + b2[j]
__global__ void agg_epilogue2_kernel(const float* __restrict__ b2,
                                     float* __restrict__ out, int n) {
    int node = blockIdx.x * blockDim.y + threadIdx.y;
    if (node >= n) return;
    int j = threadIdx.x;   // 0..63
    int beg = g_rowstart[node];
    int end = g_rowstart[node + 1];
    float acc = 0.f;
    for (int e = beg; e < end; e++) {
        int s = g_csr[e];
        acc += g_t2[(size_t)s * 128 + 64 + j];
    }
    float inv = 1.f / fmaxf((float)(end - beg), 1.f);
    out[(size_t)node * 64 + j] = g_t2[(size_t)node * 128 + j] + acc * inv + b2[j];
}

// ---------------- launch -----------------------------------------------------
extern "C" void kernel_launch(void* const* d_in, const int* in_sizes, int n_in,
                              void* d_out, int out_size) {
    const float* feat     = (const float*)d_in[0];
    const void*  src      = d_in[1];
    const void*  dst      = d_in[2];
    const float* W_self1  = (const float*)d_in[3];
    const float* W_neigh1 = (const float*)d_in[4];
    const float* b1       = (const float*)d_in[5];
    const float* W_self2  = (const float*)d_in[6];
    const float* W_neigh2 = (const float*)d_in[7];
    const float* b2       = (const float*)d_in[8];
    float* out = (float*)d_out;

    const int N = in_sizes[0] / D_IN;   // 50000
    const int E = in_sizes[1];          // 800000

    // ---- index dtype detection + CSR build (shared by both layers)
    detect_kernel<<<1, 256>>>((const int*)dst, E);
    zero_deg_kernel<<<(N + 255) / 256, 256>>>(N);
    hist_kernel<<<2048, 256>>>(dst, E);
    scan_kernel<<<1, 1024>>>(N, E);
    scatter_kernel<<<2048, 256>>>(src, dst, E);

    // ---- layer 1: feat @ [W_self1 | W_neigh1] -> g_t1 [N x 256]
    {
        dim3 grid(256 / BN, (N + BM - 1) / BM);
        gemm_dual_kernel<<<grid, 256>>>(feat, W_self1, W_neigh1, N, D_IN, D_HID, 1);
    }
    {
        dim3 block(128, 2);
        agg_epilogue1_kernel<<<(N + 1) / 2, block>>>(b1, N);
    }

    // ---- layer 2: g_h1 @ [W_self2 | W_neigh2] -> g_t2 [N x 128]
    {
        dim3 grid(128 / BN, (N + BM - 1) / BM);
        gemm_dual_kernel<<<grid, 256>>>(feat, W_self2, W_neigh2, N, D_HID, D_OUT, 2);
    }
    {
        dim3 block(64, 4);
        agg_epilogue2_kernel<<<(N + 3) / 4, block>>>(b2, out, N);
    }
}

// round 4
// speedup vs baseline: 1.2370x; 1.2370x over previous
#include <cuda_runtime.h>
#include <cuda_bf16.h>

// Problem constants (SAGEEncoder: N=50000, E=800000, IN=128, HID=128, OUT=64)
#define NMAX 50000
#define EMAX 800000
#define D_IN 128
#define D_HID 128
#define D_OUT 64

#define SCAN_TILE 512
#define SCAN_NBLK ((NMAX + SCAN_TILE - 1) / SCAN_TILE)   // 98

// ---------------- scratch (static device globals; no allocation) -------------
__device__ __align__(16) int   g_deg[NMAX];
__device__ __align__(16) int   g_rowstart[NMAX + 1];
__device__ __align__(16) int   g_cursor[NMAX];
__device__ __align__(16) int   g_csr[EMAX];
__device__ __align__(16) int   g_tilesum[SCAN_NBLK];
__device__ __align__(16) int   g_tileoff[SCAN_NBLK];
__device__ __align__(16) float g_t1[(size_t)NMAX * 256]; // [n][0:128)=feat@Wself1, [128:256)=feat@Wneigh1
__device__ __align__(16) float g_h1[(size_t)NMAX * 128]; // relu'd layer-1 output
__device__ __align__(16) float g_t2[(size_t)NMAX * 128]; // [n][0:64)=h1@Wself2, [64:128)=h1@Wneigh2
__device__ int g_is64;                                   // 1 if edge indices are int64, 0 if int32

// ---------------- index dtype detection --------------------------------------
// int64 indices < 50000 -> every high 32-bit word is 0; int32 -> odd words random.
__global__ void detect_kernel(const int* __restrict__ idx32, int E) {
    __shared__ int nz;
    if (threadIdx.x == 0) nz = 0;
    __syncthreads();
    int i = threadIdx.x;               // 2*i+1 < 512 <= E, safe either way
    if (idx32[2 * i + 1] != 0) atomicAdd(&nz, 1);
    __syncthreads();
    if (threadIdx.x == 0) g_is64 = (nz == 0) ? 1 : 0;
}

__device__ __forceinline__ int load_idx(const void* p, int e, int is64) {
    if (is64) return (int)((const long long*)p)[e];
    return ((const int*)p)[e];
}

// ---------------- CSR build --------------------------------------------------
__global__ void zero_deg_kernel(int n) {
    int i = blockIdx.x * blockDim.x + threadIdx.x;
    if (i < n) g_deg[i] = 0;
}

__global__ void hist_kernel(const void* __restrict__ dst, int E) {
    int is64 = g_is64;
    for (int e = blockIdx.x * blockDim.x + threadIdx.x; e < E; e += gridDim.x * blockDim.x)
        atomicAdd(&g_deg[load_idx(dst, e, is64)], 1);
}

// --- 3-phase parallel exclusive scan of g_deg -> g_rowstart / g_cursor -------
// phase A: per-tile reduce
__global__ void scanA_kernel(int n) {
    __shared__ int red[SCAN_TILE];
    int t = threadIdx.x;
    int i = blockIdx.x * SCAN_TILE + t;
    red[t] = (i < n) ? g_deg[i] : 0;
    __syncthreads();
    for (int off = SCAN_TILE / 2; off > 0; off >>= 1) {
        if (t < off) red[t] += red[t + off];
        __syncthreads();
    }
    if (t == 0) g_tilesum[blockIdx.x] = red[0];
}

// phase B: exclusive scan of 98 tile sums (single small block)
__global__ void scanB_kernel() {
    __shared__ int s[128];
    int t = threadIdx.x;
    s[t] = (t < SCAN_NBLK) ? g_tilesum[t] : 0;
    __syncthreads();
    for (int off = 1; off < 128; off <<= 1) {
        int v = (t >= off) ? s[t - off] : 0;
        __syncthreads();
        s[t] += v;
        __syncthreads();
    }
    if (t < SCAN_NBLK) g_tileoff[t] = (t == 0) ? 0 : s[t - 1];
}

// phase C: per-tile exclusive scan + tile offset, write rowstart/cursor
__global__ void scanC_kernel(int n, int E) {
    __shared__ int s[SCAN_TILE];
    int t = threadIdx.x;
    int i = blockIdx.x * SCAN_TILE + t;
    int v = (i < n) ? g_deg[i] : 0;
    s[t] = v;
    __syncthreads();
    for (int off = 1; off < SCAN_TILE; off <<= 1) {
        int u = (t >= off) ? s[t - off] : 0;
        __syncthreads();
        s[t] += u;
        __syncthreads();
    }
    if (i < n) {
        int excl = g_tileoff[blockIdx.x] + s[t] - v;   // inclusive - self = exclusive
        g_rowstart[i] = excl;
        g_cursor[i]   = excl;
        if (i == n - 1) g_rowstart[n] = E;
    }
}

__global__ void scatter_kernel(const void* __restrict__ src,
                               const void* __restrict__ dst, int E) {
    int is64 = g_is64;
    for (int e = blockIdx.x * blockDim.x + threadIdx.x; e < E; e += gridDim.x * blockDim.x) {
        int d = load_idx(dst, e, is64);
        int pos = atomicAdd(&g_cursor[d], 1);
        g_csr[pos] = load_idx(src, e, is64);
    }
}

// ---------------- fused dual-weight SGEMM (128x128x8, 8x8 microtile) ---------
// C[M x 2*halfN] = A[M x K] @ [W0 | W1]; W0/W1 are [K x halfN] row-major.
// layer==1: A = Aext (feat), C = g_t1.  layer==2: A = g_h1, C = g_t2.
#define GBM 128
#define GBN 128
#define GBK 8
#define GTM 8
#define GTN 8

__global__ __launch_bounds__(256) void gemm_dual_kernel(
    const float* __restrict__ Aext,
    const float* __restrict__ W0,
    const float* __restrict__ W1,
    int M, int K, int halfN, int layer)
{
    const float* __restrict__ A = (layer == 1) ? Aext : g_h1;
    float* __restrict__ C       = (layer == 1) ? g_t1 : g_t2;

    const int N  = 2 * halfN;
    const int bn = blockIdx.x * GBN;
    const int bm = blockIdx.y * GBM;

    __shared__ float As[GBK][GBM];    // transposed A tile
    __shared__ float Bs[GBK][GBN];

    const int tid = threadIdx.x;

    // A-load mapping: 128 rows x 8 k = 1024 floats; thread -> one float4 along K
    const int arow  = tid >> 1;             // 0..127
    const int acol  = (tid & 1) * 4;        // 0 or 4
    // B-load mapping: 8 rows x 128 cols; thread -> one float4 along N
    const int brow  = tid >> 5;             // 0..7
    const int bcol  = (tid & 31) * 4;       // 0..124
    // B column -> which weight matrix (float4 never straddles: halfN % 4 == 0)
    const int gcol0 = bn + bcol;
    const float* __restrict__ Wp = (gcol0 < halfN) ? W0 : W1;
    const int wc = (gcol0 < halfN) ? gcol0 : gcol0 - halfN;

    const int tx = tid & 15;                // 16 cols of threads
    const int ty = tid >> 4;                // 16 rows of threads

    float acc[GTM][GTN];
#pragma unroll
    for (int i = 0; i < GTM; i++)
#pragma unroll
        for (int j = 0; j < GTN; j++) acc[i][j] = 0.f;

    const int aRowValid = (bm + arow < M);

    for (int k0 = 0; k0 < K; k0 += GBK) {
        // load A tile (transposed into smem)
        float4 av = make_float4(0.f, 0.f, 0.f, 0.f);
        if (aRowValid)
            av = *reinterpret_cast<const float4*>(&A[(size_t)(bm + arow) * K + k0 + acol]);
        As[acol + 0][arow] = av.x;
        As[acol + 1][arow] = av.y;
        As[acol + 2][arow] = av.z;
        As[acol + 3][arow] = av.w;
        // load B tile
        float4 bv = *reinterpret_cast<const float4*>(&Wp[(size_t)(k0 + brow) * halfN + wc]);
        *reinterpret_cast<float4*>(&Bs[brow][bcol]) = bv;
        __syncthreads();

#pragma unroll
        for (int kk = 0; kk < GBK; kk++) {
            float a[GTM], b[GTN];
#pragma unroll
            for (int i = 0; i < GTM; i++) a[i] = As[kk][ty * GTM + i];
#pragma unroll
            for (int j = 0; j < GTN; j++) b[j] = Bs[kk][tx * GTN + j];
#pragma unroll
            for (int i = 0; i < GTM; i++)
#pragma unroll
                for (int j = 0; j < GTN; j++) acc[i][j] += a[i] * b[j];
        }
        __syncthreads();
    }

#pragma unroll
    for (int i = 0; i < GTM; i++) {
        int row = bm + ty * GTM + i;
        if (row < M) {
#pragma unroll
            for (int j = 0; j < GTN; j += 4) {
                float4 v = make_float4(acc[i][j], acc[i][j + 1], acc[i][j + 2], acc[i][j + 3]);
                *reinterpret_cast<float4*>(&C[(size_t)row * N + bn + tx * GTN + j]) = v;
            }
        }
    }
}

// ---------------- aggregation + epilogue -------------------------------------
// layer 1: h1[i][j] = relu( t1[i][j] + (sum_{in-edges} t1[src][128+j]) / deg + b1[j] )
__global__ void agg_epilogue1_kernel(const float* __restrict__ b1, int n) {
    int node = blockIdx.x * blockDim.y + threadIdx.y;
    if (node >= n) return;
    int j = threadIdx.x;   // 0..127
    int beg = g_rowstart[node];
    int end = g_rowstart[node + 1];
    float acc = 0.f;
    for (int e = beg; e < end; e++) {
        int s = g_csr[e];
        acc += g_t1[(size_t)s * 256 + 128 + j];
    }
    float inv = 1.f / fmaxf((float)(end - beg), 1.f);
    float v = g_t1[(size_t)node * 256 + j] + acc * inv + b1[j];
    g_h1[(size_t)node * 128 + j] = fmaxf(v, 0.f);
}

// layer 2: out[i][j] = t2[i][j] + (sum t2[src][64+j]) / deg + b2[j]
__global__ void agg_epilogue2_kernel(const float* __restrict__ b2,
                                     float* __restrict__ out, int n) {
    int node = blockIdx.x * blockDim.y + threadIdx.y;
    if (node >= n) return;
    int j = threadIdx.x;   // 0..63
    int beg = g_rowstart[node];
    int end = g_rowstart[node + 1];
    float acc = 0.f;
    for (int e = beg; e < end; e++) {
        int s = g_csr[e];
        acc += g_t2[(size_t)s * 128 + 64 + j];
    }
    float inv = 1.f / fmaxf((float)(end - beg), 1.f);
    out[(size_t)node * 64 + j] = g_t2[(size_t)node * 128 + j] + acc * inv + b2[j];
}

// ---------------- launch -----------------------------------------------------
extern "C" void kernel_launch(void* const* d_in, const int* in_sizes, int n_in,
                              void* d_out, int out_size) {
    const float* feat     = (const float*)d_in[0];
    const void*  src      = d_in[1];
    const void*  dst      = d_in[2];
    const float* W_self1  = (const float*)d_in[3];
    const float* W_neigh1 = (const float*)d_in[4];
    const float* b1       = (const float*)d_in[5];
    const float* W_self2  = (const float*)d_in[6];
    const float* W_neigh2 = (const float*)d_in[7];
    const float* b2       = (const float*)d_in[8];
    float* out = (float*)d_out;

    const int N = in_sizes[0] / D_IN;   // 50000
    const int E = in_sizes[1];          // 800000

    // ---- index dtype detection + CSR build (shared by both layers)
    detect_kernel<<<1, 256>>>((const int*)dst, E);
    zero_deg_kernel<<<(N + 255) / 256, 256>>>(N);
    hist_kernel<<<2048, 256>>>(dst, E);
    scanA_kernel<<<SCAN_NBLK, SCAN_TILE>>>(N);
    scanB_kernel<<<1, 128>>>();
    scanC_kernel<<<SCAN_NBLK, SCAN_TILE>>>(N, E);
    scatter_kernel<<<2048, 256>>>(src, dst, E);

    // ---- layer 1: feat @ [W_self1 | W_neigh1] -> g_t1 [N x 256]
    {
        dim3 grid(256 / GBN, (N + GBM - 1) / GBM);
        gemm_dual_kernel<<<grid, 256>>>(feat, W_self1, W_neigh1, N, D_IN, D_HID, 1);
    }
    {
        dim3 block(128, 2);
        agg_epilogue1_kernel<<<(N + 1) / 2, block>>>(b1, N);
    }

    // ---- layer 2: g_h1 @ [W_self2 | W_neigh2] -> g_t2 [N x 128]
    {
        dim3 grid(128 / GBN, (N + GBM - 1) / GBM);
        gemm_dual_kernel<<<grid, 256>>>(feat, W_self2, W_neigh2, N, D_HID, D_OUT, 2);
    }
    {
        dim3 block(64, 4);
        agg_epilogue2_kernel<<<(N + 3) / 4, block>>>(b2, out, N);
    }
}

// round 5
// speedup vs baseline: 1.4497x; 1.1719x over previous
#include <cuda_runtime.h>
#include <cuda_bf16.h>
#include <cstdint>

// Problem constants (SAGEEncoder: N=50000, E=800000, IN=128, HID=128, OUT=64)
#define NMAX 50000
#define EMAX 800000
#define D_IN 128
#define D_HID 128
#define D_OUT 64

#define SCAN_TILE 512
#define SCAN_NBLK ((NMAX + SCAN_TILE - 1) / SCAN_TILE)   // 98

// ---------------- scratch (static device globals; no allocation) -------------
__device__ __align__(16) int   g_deg[NMAX];
__device__ __align__(16) int   g_rowstart[NMAX + 1];
__device__ __align__(16) int   g_cursor[NMAX];
__device__ __align__(16) int   g_csr[EMAX];
__device__ __align__(16) int   g_tilesum[SCAN_NBLK];
__device__ __align__(16) int   g_tileoff[SCAN_NBLK];
__device__ __align__(16) float g_t1[(size_t)NMAX * 256]; // [n][0:128)=feat@Wself1, [128:256)=feat@Wneigh1
__device__ __align__(16) float g_h1[(size_t)NMAX * 128]; // relu'd layer-1 output
__device__ __align__(16) float g_t2[(size_t)NMAX * 128]; // [n][0:64)=h1@Wself2, [64:128)=h1@Wneigh2
__device__ int g_is64;

// ---------------- index dtype detection --------------------------------------
__global__ void detect_kernel(const int* __restrict__ idx32, int E) {
    __shared__ int nz;
    if (threadIdx.x == 0) nz = 0;
    __syncthreads();
    int i = threadIdx.x;
    if (idx32[2 * i + 1] != 0) atomicAdd(&nz, 1);
    __syncthreads();
    if (threadIdx.x == 0) g_is64 = (nz == 0) ? 1 : 0;
}

__device__ __forceinline__ int load_idx(const void* p, int e, int is64) {
    if (is64) return (int)((const long long*)p)[e];
    return ((const int*)p)[e];
}

// ---------------- CSR build --------------------------------------------------
__global__ void zero_deg_kernel(int n) {
    int i = blockIdx.x * blockDim.x + threadIdx.x;
    if (i < n) g_deg[i] = 0;
}

__global__ void hist_kernel(const void* __restrict__ dst, int E) {
    int is64 = g_is64;
    for (int e = blockIdx.x * blockDim.x + threadIdx.x; e < E; e += gridDim.x * blockDim.x)
        atomicAdd(&g_deg[load_idx(dst, e, is64)], 1);
}

__global__ void scanA_kernel(int n) {
    __shared__ int red[SCAN_TILE];
    int t = threadIdx.x;
    int i = blockIdx.x * SCAN_TILE + t;
    red[t] = (i < n) ? g_deg[i] : 0;
    __syncthreads();
    for (int off = SCAN_TILE / 2; off > 0; off >>= 1) {
        if (t < off) red[t] += red[t + off];
        __syncthreads();
    }
    if (t == 0) g_tilesum[blockIdx.x] = red[0];
}

__global__ void scanB_kernel() {
    __shared__ int s[128];
    int t = threadIdx.x;
    s[t] = (t < SCAN_NBLK) ? g_tilesum[t] : 0;
    __syncthreads();
    for (int off = 1; off < 128; off <<= 1) {
        int v = (t >= off) ? s[t - off] : 0;
        __syncthreads();
        s[t] += v;
        __syncthreads();
    }
    if (t < SCAN_NBLK) g_tileoff[t] = (t == 0) ? 0 : s[t - 1];
}

__global__ void scanC_kernel(int n, int E) {
    __shared__ int s[SCAN_TILE];
    int t = threadIdx.x;
    int i = blockIdx.x * SCAN_TILE + t;
    int v = (i < n) ? g_deg[i] : 0;
    s[t] = v;
    __syncthreads();
    for (int off = 1; off < SCAN_TILE; off <<= 1) {
        int u = (t >= off) ? s[t - off] : 0;
        __syncthreads();
        s[t] += u;
        __syncthreads();
    }
    if (i < n) {
        int excl = g_tileoff[blockIdx.x] + s[t] - v;
        g_rowstart[i] = excl;
        g_cursor[i]   = excl;
        if (i == n - 1) g_rowstart[n] = E;
    }
}

__global__ void scatter_kernel(const void* __restrict__ src,
                               const void* __restrict__ dst, int E) {
    int is64 = g_is64;
    for (int e = blockIdx.x * blockDim.x + threadIdx.x; e < E; e += gridDim.x * blockDim.x) {
        int d = load_idx(dst, e, is64);
        int pos = atomicAdd(&g_cursor[d], 1);
        g_csr[pos] = load_idx(src, e, is64);
    }
}

// ---------------- tf32-split tensor-core dual GEMM ---------------------------
// C[M x 2*halfN] = A[M x K] @ [W0 | W1] using mma.m16n8k8 tf32, 3-term split.
// layer==1: A = Aext (feat), C = g_t1.  layer==2: A = g_h1, C = g_t2.
#define TBM 128
#define TBN 128
#define TBK 32
#define APAD 8
#define ASTR (TBM + APAD)   // 136: bank = (8k+row)%32 conflict-free for frag loads
#define WSTR (TBN + APAD)   // 136

__device__ __forceinline__ uint32_t f2tf(float x) {
    uint32_t r;
    asm("cvt.rna.tf32.f32 %0, %1;" : "=r"(r) : "f"(x));
    return r;
}

__device__ __forceinline__ void mma_tf32(float* c, uint32_t a0, uint32_t a1,
                                         uint32_t a2, uint32_t a3,
                                         uint32_t b0, uint32_t b1) {
    asm volatile(
        "mma.sync.aligned.m16n8k8.row.col.f32.tf32.tf32.f32 "
        "{%0,%1,%2,%3}, {%4,%5,%6,%7}, {%8,%9}, {%0,%1,%2,%3};"
        : "+f"(c[0]), "+f"(c[1]), "+f"(c[2]), "+f"(c[3])
        : "r"(a0), "r"(a1), "r"(a2), "r"(a3), "r"(b0), "r"(b1));
}

__global__ __launch_bounds__(256) void gemm_tf32_kernel(
    const float* __restrict__ Aext,
    const float* __restrict__ W0,
    const float* __restrict__ W1,
    int M, int K, int halfN, int layer)
{
    const float* __restrict__ A = (layer == 1) ? Aext : g_h1;
    float* __restrict__ C       = (layer == 1) ? g_t1 : g_t2;

    const int N  = 2 * halfN;
    const int bn = blockIdx.x * TBN;
    const int bm = blockIdx.y * TBM;

    __shared__ float As[TBK][ASTR];   // transposed A tile: As[k][row]
    __shared__ float Ws[TBK][WSTR];   // Ws[k][col]

    const int tid  = threadIdx.x;
    const int lane = tid & 31;
    const int warp = tid >> 5;
    const int wm = warp >> 1;          // 0..3 -> 32-row slab
    const int wn = warp & 1;           // 0..1 -> 64-col slab

    // A global load mapping: row = tid>>1, k = (tid&1)*16 + {0..15}
    const int arow  = tid >> 1;
    const int akb   = (tid & 1) * 16;
    const int aValid = (bm + arow < M);
    // B global load mapping: k = tid>>3, col = (tid&7)*16 + {0..15}
    const int bkr   = tid >> 3;
    const int bcb   = (tid & 7) * 16;
    const int gcol0 = bn + bcb;
    const float* __restrict__ Wp = (gcol0 < halfN) ? W0 : W1;
    const int wc = (gcol0 < halfN) ? gcol0 : gcol0 - halfN;

    float acc[2][8][4];
#pragma unroll
    for (int i = 0; i < 2; i++)
#pragma unroll
        for (int j = 0; j < 8; j++)
#pragma unroll
            for (int q = 0; q < 4; q++) acc[i][j][q] = 0.f;

    for (int k0 = 0; k0 < K; k0 += TBK) {
        // ---- load A tile (transpose into smem) : 4 float4 per thread
#pragma unroll
        for (int v = 0; v < 4; v++) {
            float4 av = make_float4(0.f, 0.f, 0.f, 0.f);
            if (aValid)
                av = *reinterpret_cast<const float4*>(
                    &A[(size_t)(bm + arow) * K + k0 + akb + v * 4]);
            As[akb + v * 4 + 0][arow] = av.x;
            As[akb + v * 4 + 1][arow] = av.y;
            As[akb + v * 4 + 2][arow] = av.z;
            As[akb + v * 4 + 3][arow] = av.w;
        }
        // ---- load B tile : 4 float4 per thread (no transpose)
#pragma unroll
        for (int v = 0; v < 4; v++) {
            float4 bv = *reinterpret_cast<const float4*>(
                &Wp[(size_t)(k0 + bkr) * halfN + wc + v * 4]);
            *reinterpret_cast<float4*>(&Ws[bkr][bcb + v * 4]) = bv;
        }
        __syncthreads();

#pragma unroll
        for (int ks = 0; ks < TBK / 8; ks++) {
            const int kb = ks * 8;
            // B fragments for 8 n-tiles (shared across both m-tiles)
            uint32_t bhi[8][2], blo[8][2];
#pragma unroll
            for (int nj = 0; nj < 8; nj++) {
                int c = wn * 64 + nj * 8 + (lane >> 2);
                float b0 = Ws[kb + (lane & 3)][c];
                float b1 = Ws[kb + 4 + (lane & 3)][c];
                bhi[nj][0] = f2tf(b0);
                blo[nj][0] = f2tf(b0 - __uint_as_float(bhi[nj][0]));
                bhi[nj][1] = f2tf(b1);
                blo[nj][1] = f2tf(b1 - __uint_as_float(bhi[nj][1]));
            }
#pragma unroll
            for (int mi = 0; mi < 2; mi++) {
                int r = wm * 32 + mi * 16 + (lane >> 2);
                float a0 = As[kb + (lane & 3)][r];
                float a1 = As[kb + (lane & 3)][r + 8];
                float a2 = As[kb + 4 + (lane & 3)][r];
                float a3 = As[kb + 4 + (lane & 3)][r + 8];
                uint32_t ah0 = f2tf(a0), ah1 = f2tf(a1), ah2 = f2tf(a2), ah3 = f2tf(a3);
                uint32_t al0 = f2tf(a0 - __uint_as_float(ah0));
                uint32_t al1 = f2tf(a1 - __uint_as_float(ah1));
                uint32_t al2 = f2tf(a2 - __uint_as_float(ah2));
                uint32_t al3 = f2tf(a3 - __uint_as_float(ah3));
#pragma unroll
                for (int nj = 0; nj < 8; nj++) {
                    mma_tf32(acc[mi][nj], ah0, ah1, ah2, ah3, bhi[nj][0], bhi[nj][1]);
                    mma_tf32(acc[mi][nj], ah0, ah1, ah2, ah3, blo[nj][0], blo[nj][1]);
                    mma_tf32(acc[mi][nj], al0, al1, al2, al3, bhi[nj][0], bhi[nj][1]);
                }
            }
        }
        __syncthreads();
    }

    // ---- epilogue: c0/c1 -> (row, col..col+1), c2/c3 -> (row+8, ...)
#pragma unroll
    for (int mi = 0; mi < 2; mi++) {
        int r0 = bm + wm * 32 + mi * 16 + (lane >> 2);
#pragma unroll
        for (int nj = 0; nj < 8; nj++) {
            int col = bn + wn * 64 + nj * 8 + (lane & 3) * 2;
            if (r0 < M)
                *reinterpret_cast<float2*>(&C[(size_t)r0 * N + col]) =
                    make_float2(acc[mi][nj][0], acc[mi][nj][1]);
            if (r0 + 8 < M)
                *reinterpret_cast<float2*>(&C[(size_t)(r0 + 8) * N + col]) =
                    make_float2(acc[mi][nj][2], acc[mi][nj][3]);
        }
    }
}

// ---------------- aggregation + epilogue -------------------------------------
__global__ void agg_epilogue1_kernel(const float* __restrict__ b1, int n) {
    int node = blockIdx.x * blockDim.y + threadIdx.y;
    if (node >= n) return;
    int j = threadIdx.x;   // 0..127
    int beg = g_rowstart[node];
    int end = g_rowstart[node + 1];
    float acc = 0.f;
    for (int e = beg; e < end; e++) {
        int s = g_csr[e];
        acc += g_t1[(size_t)s * 256 + 128 + j];
    }
    float inv = 1.f / fmaxf((float)(end - beg), 1.f);
    float v = g_t1[(size_t)node * 256 + j] + acc * inv + b1[j];
    g_h1[(size_t)node * 128 + j] = fmaxf(v, 0.f);
}

__global__ void agg_epilogue2_kernel(const float* __restrict__ b2,
                                     float* __restrict__ out, int n) {
    int node = blockIdx.x * blockDim.y + threadIdx.y;
    if (node >= n) return;
    int j = threadIdx.x;   // 0..63
    int beg = g_rowstart[node];
    int end = g_rowstart[node + 1];
    float acc = 0.f;
    for (int e = beg; e < end; e++) {
        int s = g_csr[e];
        acc += g_t2[(size_t)s * 128 + 64 + j];
    }
    float inv = 1.f / fmaxf((float)(end - beg), 1.f);
    out[(size_t)node * 64 + j] = g_t2[(size_t)node * 128 + j] + acc * inv + b2[j];
}

// ---------------- launch -----------------------------------------------------
extern "C" void kernel_launch(void* const* d_in, const int* in_sizes, int n_in,
                              void* d_out, int out_size) {
    const float* feat     = (const float*)d_in[0];
    const void*  src      = d_in[1];
    const void*  dst      = d_in[2];
    const float* W_self1  = (const float*)d_in[3];
    const float* W_neigh1 = (const float*)d_in[4];
    const float* b1       = (const float*)d_in[5];
    const float* W_self2  = (const float*)d_in[6];
    const float* W_neigh2 = (const float*)d_in[7];
    const float* b2       = (const float*)d_in[8];
    float* out = (float*)d_out;

    const int N = in_sizes[0] / D_IN;   // 50000
    const int E = in_sizes[1];          // 800000

    // ---- index dtype detection + CSR build (shared by both layers)
    detect_kernel<<<1, 256>>>((const int*)dst, E);
    zero_deg_kernel<<<(N + 255) / 256, 256>>>(N);
    hist_kernel<<<2048, 256>>>(dst, E);
    scanA_kernel<<<SCAN_NBLK, SCAN_TILE>>>(N);
    scanB_kernel<<<1, 128>>>();
    scanC_kernel<<<SCAN_NBLK, SCAN_TILE>>>(N, E);
    scatter_kernel<<<2048, 256>>>(src, dst, E);

    // ---- layer 1: feat @ [W_self1 | W_neigh1] -> g_t1 [N x 256]
    {
        dim3 grid(256 / TBN, (N + TBM - 1) / TBM);
        gemm_tf32_kernel<<<grid, 256>>>(feat, W_self1, W_neigh1, N, D_IN, D_HID, 1);
    }
    {
        dim3 block(128, 2);
        agg_epilogue1_kernel<<<(N + 1) / 2, block>>>(b1, N);
    }

    // ---- layer 2: g_h1 @ [W_self2 | W_neigh2] -> g_t2 [N x 128]
    {
        dim3 grid(128 / TBN, (N + TBM - 1) / TBM);
        gemm_tf32_kernel<<<grid, 256>>>(feat, W_self2, W_neigh2, N, D_HID, D_OUT, 2);
    }
    {
        dim3 block(64, 4);
        agg_epilogue2_kernel<<<(N + 3) / 4, block>>>(b2, out, N);
    }
}